// round 11
// baseline (speedup 1.0000x reference)
#include <cuda_runtime.h>
#include <cuda_bf16.h>

#define Nn  8
#define Cc  64
#define Hh  128
#define Ww  512
#define CoN 64
#define HW  (Hh * Ww)      // 65536
#define NOFF 18
#define SSTR 68            // deform tile stride: 272B, 16B-aligned, conflict-free
#define XSTR 136           // offset-conv x-tile stride

// Scratch: offsets and tf32 B-fragment tables.
__device__ float  g_off[(size_t)Nn * NOFF * HW];   // ~36 MB
__device__ float2 g_wfrag[9 * 8 * 8 * 32];         // deform B frags [t][k][ni][lane]
__device__ float2 g_wofrag[72 * 3 * 32];           // offset B frags

__device__ __forceinline__ unsigned f2tf32(float v) {
    unsigned u;
    asm("cvt.rna.tf32.f32 %0, %1;" : "=r"(u) : "f"(v));
    return u;
}

// ---------------------------------------------------------------------------
// Kernel 0a: deform B fragments (m16n8k8 tf32).
// ---------------------------------------------------------------------------
__global__ void wfrag_kernel(const float* __restrict__ wdef) {
    int idx = blockIdx.x * 256 + threadIdx.x;
    if (idx >= 9 * 8 * 8 * 32) return;
    int lane = idx & 31;
    int ni   = (idx >> 5) & 7;
    int k    = (idx >> 8) & 7;
    int t    = idx >> 11;
    int c = 8 * k + (lane & 3);
    int o = 8 * ni + (lane >> 2);
    float b0 = wdef[(o * 64 + c) * 9 + t];
    float b1 = wdef[(o * 64 + c + 4) * 9 + t];
    g_wfrag[idx] = make_float2(__uint_as_float(f2tf32(b0)),
                               __uint_as_float(f2tf32(b1)));
}

// ---------------------------------------------------------------------------
// Kernel 0b: offset-conv B fragments (oc padded 18 -> 24).
// ---------------------------------------------------------------------------
__global__ void wofrag_kernel(const float* __restrict__ woff) {
    int idx = blockIdx.x * 256 + threadIdx.x;
    if (idx >= 72 * 3 * 32) return;
    int lane = idx & 31;
    int rem  = idx >> 5;
    int ni   = rem % 3;
    int ks   = rem / 3;
    int gr = lane >> 2, tc = lane & 3;
    int k0 = 8 * ks + tc;
    int oc = 8 * ni + gr;
    float b0 = (oc < 18) ? woff[oc * 576 + k0]     : 0.0f;
    float b1 = (oc < 18) ? woff[oc * 576 + k0 + 4] : 0.0f;
    g_wofrag[(ks * 3 + ni) * 32 + lane] =
        make_float2(__uint_as_float(f2tf32(b0)), __uint_as_float(f2tf32(b1)));
}

// ---------------------------------------------------------------------------
// Kernel 1: offset conv via tf32 MMA.
// Same loads / smem layout / MMA stream as Round 4; ALU fixes only:
//  - fill loop uses incremental (r,col) instead of div/mod (r = c*3+i)
//  - off0/off1 (per kk,tc) hoisted out of the ch loop into register arrays
// ---------------------------------------------------------------------------
__global__ void __launch_bounds__(128) offset_mma_kernel(
    const float* __restrict__ xin,
    const float* __restrict__ boff)
{
    __shared__ float sx[24 * XSTR];

    int tid  = threadIdx.x;
    int lane = tid & 31;
    int warp = tid >> 5;
    int gr   = lane >> 2;
    int tc   = lane & 3;

    int x0 = blockIdx.x * 128;
    int y  = blockIdx.y;
    int n  = blockIdx.z;

    float acc[2][3][4];
#pragma unroll
    for (int ni = 0; ni < 3; ni++) {
        int oc = 8 * ni + 2 * tc;
        float blo = (oc < 18)     ? __ldg(&boff[oc])     : 0.0f;
        float bhi = (oc + 1 < 18) ? __ldg(&boff[oc + 1]) : 0.0f;
#pragma unroll
        for (int mi = 0; mi < 2; mi++) {
            acc[mi][ni][0] = blo; acc[mi][ni][1] = bhi;
            acc[mi][ni][2] = blo; acc[mi][ni][3] = bhi;
        }
    }

    // hoisted A-fragment smem offsets: depend only on (kk, tc)
    int aoff0[9], aoff1[9];
#pragma unroll
    for (int kk = 0; kk < 9; kk++) {
        int kl = 8 * kk + tc;
        int c0 = kl / 9,  t0 = kl - 9 * c0;
        int i0 = t0 / 3,  j0 = t0 - 3 * i0;
        int kl2 = kl + 4;
        int c1 = kl2 / 9, t1 = kl2 - 9 * c1;
        int i1 = t1 / 3,  j1 = t1 - 3 * i1;
        aoff0[kk] = (c0 * 3 + i0) * XSTR + j0;
        aoff1[kk] = (c1 * 3 + i1) * XSTR + j1;
    }

    const float* xb = xin + (size_t)n * Cc * HW;

    for (int ch = 0; ch < 8; ch++) {
        __syncthreads();
        {   // fill: same element order/addresses as idx = tid + 128*s,
            // idx = r*130 + col, r = c*3 + i; incremental bookkeeping.
            int r = 0, col = tid, i = 0, c = 0;
#pragma unroll
            for (int s = 0; s < 24; s++) {
                int yy = y + i - 1;
                int xx = x0 + col - 1;
                float v = 0.0f;
                if (yy >= 0 && yy < Hh && xx >= 0 && xx < Ww)
                    v = xb[(size_t)(ch * 8 + c) * HW + yy * Ww + xx];
                sx[r * XSTR + col] = __uint_as_float(f2tf32(v));
                col += 128;
                if (col >= 130) {
                    col -= 130;
                    r++;
                    if (++i == 3) { i = 0; c++; }
                }
            }
            if (tid < 48) {   // tail: idx = 3072+tid -> r=23 (c=7,i=2), col=82+tid
                int colr = 82 + tid;
                int yy = y + 1;          // i=2 -> y+2-1
                int xx = x0 + colr - 1;
                float v = 0.0f;
                if (yy >= 0 && yy < Hh && xx >= 0 && xx < Ww)
                    v = xb[(size_t)(ch * 8 + 7) * HW + yy * Ww + xx];
                sx[23 * XSTR + colr] = __uint_as_float(f2tf32(v));
            }
        }
        __syncthreads();

#pragma unroll
        for (int kk = 0; kk < 9; kk++) {
            int off0 = aoff0[kk];
            int off1 = aoff1[kk];

            const float2* wf = g_wofrag + (size_t)(ch * 9 + kk) * 96;
            float2 bfr[3];
#pragma unroll
            for (int ni = 0; ni < 3; ni++) bfr[ni] = __ldg(&wf[ni * 32 + lane]);

#pragma unroll
            for (int mi = 0; mi < 2; mi++) {
                int m = warp * 32 + mi * 16 + gr;
                unsigned a0 = __float_as_uint(sx[off0 + m]);
                unsigned a1 = __float_as_uint(sx[off0 + m + 8]);
                unsigned a2 = __float_as_uint(sx[off1 + m]);
                unsigned a3 = __float_as_uint(sx[off1 + m + 8]);
#pragma unroll
                for (int ni = 0; ni < 3; ni++) {
                    unsigned b0 = __float_as_uint(bfr[ni].x);
                    unsigned b1 = __float_as_uint(bfr[ni].y);
                    asm volatile(
                        "mma.sync.aligned.m16n8k8.row.col.f32.tf32.tf32.f32 "
                        "{%0,%1,%2,%3}, {%4,%5,%6,%7}, {%8,%9}, {%0,%1,%2,%3};"
                        : "+f"(acc[mi][ni][0]), "+f"(acc[mi][ni][1]),
                          "+f"(acc[mi][ni][2]), "+f"(acc[mi][ni][3])
                        : "r"(a0), "r"(a1), "r"(a2), "r"(a3),
                          "r"(b0), "r"(b1));
                }
            }
        }
    }

    size_t ob = (size_t)n * NOFF * HW + (size_t)y * Ww + x0;
#pragma unroll
    for (int ni = 0; ni < 3; ni++) {
        int oc = 8 * ni + 2 * tc;
#pragma unroll
        for (int mi = 0; mi < 2; mi++) {
            int pr = warp * 32 + mi * 16 + gr;
            if (oc < 18) {
                g_off[ob + (size_t)oc * HW + pr]     = acc[mi][ni][0];
                g_off[ob + (size_t)oc * HW + pr + 8] = acc[mi][ni][2];
            }
            if (oc + 1 < 18) {
                g_off[ob + (size_t)(oc + 1) * HW + pr]     = acc[mi][ni][1];
                g_off[ob + (size_t)(oc + 1) * HW + pr + 8] = acc[mi][ni][3];
            }
        }
    }
}

// ---------------------------------------------------------------------------
// Kernel 2: deformable conv — Round-9 version verbatim (best: 597 us).
// tf32 MMA, och split across warps, double-buffered tile, one pair-barrier
// per tap, offset prefetch.
// ---------------------------------------------------------------------------
__global__ void __launch_bounds__(128, 6) deform_mma_kernel(
    const float* __restrict__ xin,
    const float* __restrict__ bdef,
    float* __restrict__ out)
{
    __shared__ __align__(16) float sS[2][64 * SSTR];   // 2 x 17408 B

    int tid  = threadIdx.x;
    int lane = tid & 31;
    int warp = tid >> 5;
    int g    = warp & 1;      // pixel group
    int h    = warp >> 1;     // channel half (gather ch + MMA och)
    int gr   = lane >> 2;
    int tc   = lane & 3;

    int x0  = blockIdx.x * 64;
    int y   = blockIdx.y;
    int n   = blockIdx.z;
    int pxl = tid & 63;       // gather pixel within CTA
    int xg  = x0 + pxl;

    float acc[2][4][4];
#pragma unroll
    for (int ni = 0; ni < 4; ni++) {
        int ni_g = 4 * h + ni;
        float blo = __ldg(&bdef[8 * ni_g + 2 * tc]);
        float bhi = __ldg(&bdef[8 * ni_g + 2 * tc + 1]);
#pragma unroll
        for (int mi = 0; mi < 2; mi++) {
            acc[mi][ni][0] = blo; acc[mi][ni][1] = bhi;
            acc[mi][ni][2] = blo; acc[mi][ni][3] = bhi;
        }
    }

    const float* xb   = xin + (size_t)n * Cc * HW + (size_t)(h * 32) * HW;
    const float* offb = g_off + (size_t)n * NOFF * HW + (size_t)y * Ww + xg;

    // prefetch tap-0 offsets
    float dy = offb[0];
    float dx = offb[(size_t)HW];

    for (int t = 0; t < 9; t++) {
        int i = t / 3, j = t % 3;
        float py  = (float)(y + i - 1) + dy;
        float pxf = (float)(xg + j - 1) + dx;

        // prefetch next tap's offsets (overlaps gather + MMA)
        if (t < 8) {
            dy = offb[(size_t)(2 * t + 2) * HW];
            dx = offb[(size_t)(2 * t + 3) * HW];
        }

        float fy = floorf(py), fx = floorf(pxf);
        float wy1 = py - fy, wx1 = pxf - fx;
        float wy0 = 1.0f - wy1, wx0 = 1.0f - wx1;
        int iy0 = (int)fy, ix0 = (int)fx;
        int iy1 = iy0 + 1, ix1 = ix0 + 1;

        float gy0 = (iy0 >= 0 && iy0 < Hh) ? wy0 : 0.0f;
        float gy1 = (iy1 >= 0 && iy1 < Hh) ? wy1 : 0.0f;
        float gx0 = (ix0 >= 0 && ix0 < Ww) ? wx0 : 0.0f;
        float gx1 = (ix1 >= 0 && ix1 < Ww) ? wx1 : 0.0f;
        float c00 = gy0 * gx0, c01 = gy0 * gx1;
        float c10 = gy1 * gx0, c11 = gy1 * gx1;

        int yc0 = min(max(iy0, 0), Hh - 1), yc1 = min(max(iy1, 0), Hh - 1);
        int xc0 = min(max(ix0, 0), Ww - 1), xc1 = min(max(ix1, 0), Ww - 1);
        int o00 = yc0 * Ww + xc0, o01 = yc0 * Ww + xc1;
        int o10 = yc1 * Ww + xc0, o11 = yc1 * Ww + xc1;

        float* buf = sS[t & 1];

        {   // gather 32 channels of pixel pxl into this buffer's quadrant
            float4* srow = (float4*)(buf + pxl * SSTR + 32 * h);
            const float* p = xb;
#pragma unroll
            for (int q = 0; q < 8; q++) {
                float4 v;
                {
                    float a = c00 * p[o00];
                    a = fmaf(c01, p[o01], a);
                    a = fmaf(c10, p[o10], a);
                    a = fmaf(c11, p[o11], a);
                    v.x = __uint_as_float(f2tf32(a));  p += HW;
                }
                {
                    float a = c00 * p[o00];
                    a = fmaf(c01, p[o01], a);
                    a = fmaf(c10, p[o10], a);
                    a = fmaf(c11, p[o11], a);
                    v.y = __uint_as_float(f2tf32(a));  p += HW;
                }
                {
                    float a = c00 * p[o00];
                    a = fmaf(c01, p[o01], a);
                    a = fmaf(c10, p[o10], a);
                    a = fmaf(c11, p[o11], a);
                    v.z = __uint_as_float(f2tf32(a));  p += HW;
                }
                {
                    float a = c00 * p[o00];
                    a = fmaf(c01, p[o01], a);
                    a = fmaf(c10, p[o10], a);
                    a = fmaf(c11, p[o11], a);
                    v.w = __uint_as_float(f2tf32(a));  p += HW;
                }
                srow[q] = v;
            }
        }

        // single pair barrier per tap: all quadrants of buf[t&1] written
        asm volatile("bar.sync %0, %1;" :: "r"(1 + g), "r"(64) : "memory");

        const float2* wf = g_wfrag + (size_t)t * 8 * 8 * 32;
#pragma unroll
        for (int k = 0; k < 8; k++) {
            unsigned a[2][4];
#pragma unroll
            for (int mi = 0; mi < 2; mi++) {
                const float* base = buf + (32 * g + mi * 16 + gr) * SSTR + 8 * k + tc;
                a[mi][0] = __float_as_uint(base[0]);
                a[mi][1] = __float_as_uint(base[8 * SSTR]);
                a[mi][2] = __float_as_uint(base[4]);
                a[mi][3] = __float_as_uint(base[8 * SSTR + 4]);
            }
#pragma unroll
            for (int ni = 0; ni < 4; ni++) {
                int ni_g = 4 * h + ni;
                float2 b = __ldg(&wf[(k * 8 + ni_g) * 32 + lane]);
                unsigned b0 = __float_as_uint(b.x);
                unsigned b1 = __float_as_uint(b.y);
#pragma unroll
                for (int mi = 0; mi < 2; mi++) {
                    asm volatile(
                        "mma.sync.aligned.m16n8k8.row.col.f32.tf32.tf32.f32 "
                        "{%0,%1,%2,%3}, {%4,%5,%6,%7}, {%8,%9}, {%0,%1,%2,%3};"
                        : "+f"(acc[mi][ni][0]), "+f"(acc[mi][ni][1]),
                          "+f"(acc[mi][ni][2]), "+f"(acc[mi][ni][3])
                        : "r"(a[mi][0]), "r"(a[mi][1]), "r"(a[mi][2]), "r"(a[mi][3]),
                          "r"(b0), "r"(b1));
                }
            }
        }
    }

    // epilogue: warp writes its 32 px x 32 och
    size_t ob = (size_t)n * CoN * HW + (size_t)y * Ww + x0;
#pragma unroll
    for (int ni = 0; ni < 4; ni++) {
        int o = 8 * (4 * h + ni) + 2 * tc;
#pragma unroll
        for (int mi = 0; mi < 2; mi++) {
            int pr = 32 * g + mi * 16 + gr;
            out[ob + (size_t)o * HW + pr]           = acc[mi][ni][0];
            out[ob + (size_t)(o + 1) * HW + pr]     = acc[mi][ni][1];
            out[ob + (size_t)o * HW + pr + 8]       = acc[mi][ni][2];
            out[ob + (size_t)(o + 1) * HW + pr + 8] = acc[mi][ni][3];
        }
    }
}

// ---------------------------------------------------------------------------
extern "C" void kernel_launch(void* const* d_in, const int* in_sizes, int n_in,
                              void* d_out, int out_size)
{
    const float* x    = (const float*)d_in[0];
    const float* woff = (const float*)d_in[1];
    const float* boff = (const float*)d_in[2];
    const float* wdef = (const float*)d_in[3];
    const float* bdef = (const float*)d_in[4];
    float* out = (float*)d_out;

    wfrag_kernel<<<(9 * 8 * 8 * 32 + 255) / 256, 256>>>(wdef);
    wofrag_kernel<<<(72 * 3 * 32 + 255) / 256, 256>>>(woff);
    offset_mma_kernel<<<dim3(Ww / 128, Hh, Nn), 128>>>(x, boff);
    deform_mma_kernel<<<dim3(Ww / 64, Hh, Nn), 128>>>(x, bdef, out);
}

// round 12
// speedup vs baseline: 1.0995x; 1.0995x over previous
#include <cuda_runtime.h>
#include <cuda_bf16.h>

#define Nn  8
#define Cc  64
#define Hh  128
#define Ww  512
#define CoN 64
#define HW  (Hh * Ww)      // 65536
#define NOFF 18
#define SSTR 68            // deform tile stride: 272B, 16B-aligned, conflict-free

// Scratch: offsets and tf32 B-fragment tables.
__device__ float  g_off[(size_t)Nn * NOFF * HW];   // ~36 MB
__device__ float2 g_wfrag[9 * 8 * 8 * 32];         // deform B frags [t][k][ni][lane]
__device__ float2 g_wofrag4[72 * 4 * 32];          // offset B frags, 4 ni (oc pad 32)

__device__ __forceinline__ unsigned f2tf32(float v) {
    unsigned u;
    asm("cvt.rna.tf32.f32 %0, %1;" : "=r"(u) : "f"(v));
    return u;
}

// ---------------------------------------------------------------------------
// Kernel 0a: deform B fragments (m16n8k8 tf32).
// ---------------------------------------------------------------------------
__global__ void wfrag_kernel(const float* __restrict__ wdef) {
    int idx = blockIdx.x * 256 + threadIdx.x;
    if (idx >= 9 * 8 * 8 * 32) return;
    int lane = idx & 31;
    int ni   = (idx >> 5) & 7;
    int k    = (idx >> 8) & 7;
    int t    = idx >> 11;
    int c = 8 * k + (lane & 3);
    int o = 8 * ni + (lane >> 2);
    float b0 = wdef[(o * 64 + c) * 9 + t];
    float b1 = wdef[(o * 64 + c + 4) * 9 + t];
    g_wfrag[idx] = make_float2(__uint_as_float(f2tf32(b0)),
                               __uint_as_float(f2tf32(b1)));
}

// ---------------------------------------------------------------------------
// Kernel 0b: offset-conv B fragments, oc padded 18 -> 32 (4 ni frags).
// ---------------------------------------------------------------------------
__global__ void wofrag4_kernel(const float* __restrict__ woff) {
    int idx = blockIdx.x * 256 + threadIdx.x;
    if (idx >= 72 * 4 * 32) return;
    int lane = idx & 31;
    int ni   = (idx >> 5) & 3;
    int ks   = idx >> 7;
    int gr = lane >> 2, tc = lane & 3;
    int k0 = 8 * ks + tc;
    int oc = 8 * ni + gr;
    float b0 = (oc < 18) ? woff[oc * 576 + k0]     : 0.0f;
    float b1 = (oc < 18) ? woff[oc * 576 + k0 + 4] : 0.0f;
    g_wofrag4[idx] =
        make_float2(__uint_as_float(f2tf32(b0)), __uint_as_float(f2tf32(b1)));
}

// ---------------------------------------------------------------------------
// FUSED kernel: phase A computes this CTA's 64 pixels' offsets (tf32 MMA,
// shifted-view im2col, warps split g=px-half / h=oc-half), writes them to
// g_off, syncs, then runs the Round-9 deform tap loop verbatim.
// ---------------------------------------------------------------------------
__global__ void __launch_bounds__(128, 6) deform_fused_kernel(
    const float* __restrict__ xin,
    const float* __restrict__ boff,
    const float* __restrict__ bdef,
    float* __restrict__ out)
{
    __shared__ __align__(16) float sS[2][64 * SSTR];   // 2 x 17408 B

    int tid  = threadIdx.x;
    int lane = tid & 31;
    int warp = tid >> 5;
    int g    = warp & 1;      // pixel group
    int h    = warp >> 1;     // channel half / oc half
    int gr   = lane >> 2;
    int tc   = lane & 3;

    int x0  = blockIdx.x * 64;
    int y   = blockIdx.y;
    int n   = blockIdx.z;
    int pxl = tid & 63;
    int xg  = x0 + pxl;

    const float* xb0 = xin + (size_t)n * Cc * HW;
    size_t oob = (size_t)n * NOFF * HW + (size_t)y * Ww + x0;

    // ===================== Phase A: offset conv (64 px) =====================
    {
        float* sxA = &sS[0][0];    // 24 rows x 68 cols (6528 B)
        float oacc[2][2][4];
#pragma unroll
        for (int ni = 0; ni < 2; ni++) {
            int oc = 8 * (2 * h + ni) + 2 * tc;
            float blo = (oc < 18)     ? __ldg(&boff[oc])     : 0.0f;
            float bhi = (oc + 1 < 18) ? __ldg(&boff[oc + 1]) : 0.0f;
#pragma unroll
            for (int mi = 0; mi < 2; mi++) {
                oacc[mi][ni][0] = blo; oacc[mi][ni][1] = bhi;
                oacc[mi][ni][2] = blo; oacc[mi][ni][3] = bhi;
            }
        }

        for (int ch = 0; ch < 8; ch++) {
            __syncthreads();
            // fill 8 channels x 3 rows x 66 cols (halo 1 each side)
            for (int idx = tid; idx < 1584; idx += 128) {
                int r   = idx / 66;          // r = c*3 + i
                int col = idx - 66 * r;
                int c   = r / 3;
                int i   = r - 3 * c;
                int yy = y + i - 1;
                int xx = x0 + col - 1;
                float v = 0.0f;
                if (yy >= 0 && yy < Hh && xx >= 0 && xx < Ww)
                    v = xb0[(size_t)(ch * 8 + c) * HW + yy * Ww + xx];
                sxA[r * SSTR + col] = __uint_as_float(f2tf32(v));
            }
            __syncthreads();

#pragma unroll
            for (int kk = 0; kk < 9; kk++) {
                int kl = 8 * kk + tc;
                int c0 = kl / 9,  t0 = kl - 9 * c0;
                int i0 = t0 / 3,  j0 = t0 - 3 * i0;
                int kl2 = kl + 4;
                int c1 = kl2 / 9, t1 = kl2 - 9 * c1;
                int i1 = t1 / 3,  j1 = t1 - 3 * i1;
                int off0 = (c0 * 3 + i0) * SSTR + j0;
                int off1 = (c1 * 3 + i1) * SSTR + j1;

                const float2* wf = g_wofrag4 + (size_t)(ch * 9 + kk) * 128;
                float2 bfr[2];
#pragma unroll
                for (int ni = 0; ni < 2; ni++)
                    bfr[ni] = __ldg(&wf[(2 * h + ni) * 32 + lane]);

#pragma unroll
                for (int mi = 0; mi < 2; mi++) {
                    int m = g * 32 + mi * 16 + gr;
                    unsigned a0 = __float_as_uint(sxA[off0 + m]);
                    unsigned a1 = __float_as_uint(sxA[off0 + m + 8]);
                    unsigned a2 = __float_as_uint(sxA[off1 + m]);
                    unsigned a3 = __float_as_uint(sxA[off1 + m + 8]);
#pragma unroll
                    for (int ni = 0; ni < 2; ni++) {
                        unsigned b0 = __float_as_uint(bfr[ni].x);
                        unsigned b1 = __float_as_uint(bfr[ni].y);
                        asm volatile(
                            "mma.sync.aligned.m16n8k8.row.col.f32.tf32.tf32.f32 "
                            "{%0,%1,%2,%3}, {%4,%5,%6,%7}, {%8,%9}, {%0,%1,%2,%3};"
                            : "+f"(oacc[mi][ni][0]), "+f"(oacc[mi][ni][1]),
                              "+f"(oacc[mi][ni][2]), "+f"(oacc[mi][ni][3])
                            : "r"(a0), "r"(a1), "r"(a2), "r"(a3),
                              "r"(b0), "r"(b1));
                    }
                }
            }
        }

        // write this CTA's 64 pixels' offsets (18 channels) to g_off
#pragma unroll
        for (int ni = 0; ni < 2; ni++) {
            int oc = 8 * (2 * h + ni) + 2 * tc;
#pragma unroll
            for (int mi = 0; mi < 2; mi++) {
                int pr = g * 32 + mi * 16 + gr;
                if (oc < 18) {
                    g_off[oob + (size_t)oc * HW + pr]     = oacc[mi][ni][0];
                    g_off[oob + (size_t)oc * HW + pr + 8] = oacc[mi][ni][2];
                }
                if (oc + 1 < 18) {
                    g_off[oob + (size_t)(oc + 1) * HW + pr]     = oacc[mi][ni][1];
                    g_off[oob + (size_t)(oc + 1) * HW + pr + 8] = oacc[mi][ni][3];
                }
            }
        }
        __syncthreads();   // offsets visible to whole CTA; sS free for tap loop
    }

    // ===================== Phase B: deform tap loop (Round 9) ===============
    float acc[2][4][4];
#pragma unroll
    for (int ni = 0; ni < 4; ni++) {
        int ni_g = 4 * h + ni;
        float blo = __ldg(&bdef[8 * ni_g + 2 * tc]);
        float bhi = __ldg(&bdef[8 * ni_g + 2 * tc + 1]);
#pragma unroll
        for (int mi = 0; mi < 2; mi++) {
            acc[mi][ni][0] = blo; acc[mi][ni][1] = bhi;
            acc[mi][ni][2] = blo; acc[mi][ni][3] = bhi;
        }
    }

    const float* xb   = xb0 + (size_t)(h * 32) * HW;
    const float* offb = g_off + oob + pxl;

    float dy = offb[0];
    float dx = offb[(size_t)HW];

    for (int t = 0; t < 9; t++) {
        int i = t / 3, j = t % 3;
        float py  = (float)(y + i - 1) + dy;
        float pxf = (float)(xg + j - 1) + dx;

        if (t < 8) {
            dy = offb[(size_t)(2 * t + 2) * HW];
            dx = offb[(size_t)(2 * t + 3) * HW];
        }

        float fy = floorf(py), fx = floorf(pxf);
        float wy1 = py - fy, wx1 = pxf - fx;
        float wy0 = 1.0f - wy1, wx0 = 1.0f - wx1;
        int iy0 = (int)fy, ix0 = (int)fx;
        int iy1 = iy0 + 1, ix1 = ix0 + 1;

        float gy0 = (iy0 >= 0 && iy0 < Hh) ? wy0 : 0.0f;
        float gy1 = (iy1 >= 0 && iy1 < Hh) ? wy1 : 0.0f;
        float gx0 = (ix0 >= 0 && ix0 < Ww) ? wx0 : 0.0f;
        float gx1 = (ix1 >= 0 && ix1 < Ww) ? wx1 : 0.0f;
        float c00 = gy0 * gx0, c01 = gy0 * gx1;
        float c10 = gy1 * gx0, c11 = gy1 * gx1;

        int yc0 = min(max(iy0, 0), Hh - 1), yc1 = min(max(iy1, 0), Hh - 1);
        int xc0 = min(max(ix0, 0), Ww - 1), xc1 = min(max(ix1, 0), Ww - 1);
        int o00 = yc0 * Ww + xc0, o01 = yc0 * Ww + xc1;
        int o10 = yc1 * Ww + xc0, o11 = yc1 * Ww + xc1;

        float* buf = sS[t & 1];

        {   // gather 32 channels of pixel pxl into this buffer's quadrant
            float4* srow = (float4*)(buf + pxl * SSTR + 32 * h);
            const float* p = xb;
#pragma unroll
            for (int q = 0; q < 8; q++) {
                float4 v;
                {
                    float a = c00 * p[o00];
                    a = fmaf(c01, p[o01], a);
                    a = fmaf(c10, p[o10], a);
                    a = fmaf(c11, p[o11], a);
                    v.x = __uint_as_float(f2tf32(a));  p += HW;
                }
                {
                    float a = c00 * p[o00];
                    a = fmaf(c01, p[o01], a);
                    a = fmaf(c10, p[o10], a);
                    a = fmaf(c11, p[o11], a);
                    v.y = __uint_as_float(f2tf32(a));  p += HW;
                }
                {
                    float a = c00 * p[o00];
                    a = fmaf(c01, p[o01], a);
                    a = fmaf(c10, p[o10], a);
                    a = fmaf(c11, p[o11], a);
                    v.z = __uint_as_float(f2tf32(a));  p += HW;
                }
                {
                    float a = c00 * p[o00];
                    a = fmaf(c01, p[o01], a);
                    a = fmaf(c10, p[o10], a);
                    a = fmaf(c11, p[o11], a);
                    v.w = __uint_as_float(f2tf32(a));  p += HW;
                }
                srow[q] = v;
            }
        }

        // single pair barrier per tap
        asm volatile("bar.sync %0, %1;" :: "r"(1 + g), "r"(64) : "memory");

        const float2* wf = g_wfrag + (size_t)t * 8 * 8 * 32;
#pragma unroll
        for (int k = 0; k < 8; k++) {
            unsigned a[2][4];
#pragma unroll
            for (int mi = 0; mi < 2; mi++) {
                const float* base = buf + (32 * g + mi * 16 + gr) * SSTR + 8 * k + tc;
                a[mi][0] = __float_as_uint(base[0]);
                a[mi][1] = __float_as_uint(base[8 * SSTR]);
                a[mi][2] = __float_as_uint(base[4]);
                a[mi][3] = __float_as_uint(base[8 * SSTR + 4]);
            }
#pragma unroll
            for (int ni = 0; ni < 4; ni++) {
                int ni_g = 4 * h + ni;
                float2 b = __ldg(&wf[(k * 8 + ni_g) * 32 + lane]);
                unsigned b0 = __float_as_uint(b.x);
                unsigned b1 = __float_as_uint(b.y);
#pragma unroll
                for (int mi = 0; mi < 2; mi++) {
                    asm volatile(
                        "mma.sync.aligned.m16n8k8.row.col.f32.tf32.tf32.f32 "
                        "{%0,%1,%2,%3}, {%4,%5,%6,%7}, {%8,%9}, {%0,%1,%2,%3};"
                        : "+f"(acc[mi][ni][0]), "+f"(acc[mi][ni][1]),
                          "+f"(acc[mi][ni][2]), "+f"(acc[mi][ni][3])
                        : "r"(a[mi][0]), "r"(a[mi][1]), "r"(a[mi][2]), "r"(a[mi][3]),
                          "r"(b0), "r"(b1));
                }
            }
        }
    }

    // epilogue: warp writes its 32 px x 32 och
    size_t ob = (size_t)n * CoN * HW + (size_t)y * Ww + x0;
#pragma unroll
    for (int ni = 0; ni < 4; ni++) {
        int o = 8 * (4 * h + ni) + 2 * tc;
#pragma unroll
        for (int mi = 0; mi < 2; mi++) {
            int pr = 32 * g + mi * 16 + gr;
            out[ob + (size_t)o * HW + pr]           = acc[mi][ni][0];
            out[ob + (size_t)(o + 1) * HW + pr]     = acc[mi][ni][1];
            out[ob + (size_t)o * HW + pr + 8]       = acc[mi][ni][2];
            out[ob + (size_t)(o + 1) * HW + pr + 8] = acc[mi][ni][3];
        }
    }
}

// ---------------------------------------------------------------------------
extern "C" void kernel_launch(void* const* d_in, const int* in_sizes, int n_in,
                              void* d_out, int out_size)
{
    const float* x    = (const float*)d_in[0];
    const float* woff = (const float*)d_in[1];
    const float* boff = (const float*)d_in[2];
    const float* wdef = (const float*)d_in[3];
    const float* bdef = (const float*)d_in[4];
    float* out = (float*)d_out;

    wfrag_kernel<<<(9 * 8 * 8 * 32 + 255) / 256, 256>>>(wdef);
    wofrag4_kernel<<<(72 * 4 * 32 + 255) / 256, 256>>>(woff);
    deform_fused_kernel<<<dim3(Ww / 64, Hh, Nn), 128>>>(x, boff, bdef, out);
}

// round 13
// speedup vs baseline: 1.1900x; 1.0824x over previous
#include <cuda_runtime.h>
#include <cuda_bf16.h>

#define Nn  8
#define Cc  64
#define Hh  128
#define Ww  512
#define CoN 64
#define HW  (Hh * Ww)      // 65536
#define NOFF 18
#define SSTR 68            // deform tile stride: 272B, 16B-aligned, conflict-free
#define XSTR 136           // offset-conv x-tile stride

// Scratch: offsets and tf32 B-fragment tables.
__device__ float  g_off[(size_t)Nn * NOFF * HW];   // ~36 MB
__device__ float2 g_wfrag[9 * 8 * 8 * 32];         // deform B frags [t][k][ni][lane]
__device__ float2 g_wofrag[72 * 3 * 32];           // offset B frags

__device__ __forceinline__ unsigned f2tf32(float v) {
    unsigned u;
    asm("cvt.rna.tf32.f32 %0, %1;" : "=r"(u) : "f"(v));
    return u;
}

// ---------------------------------------------------------------------------
// Kernel 0a: deform B fragments (m16n8k8 tf32).
// ---------------------------------------------------------------------------
__global__ void wfrag_kernel(const float* __restrict__ wdef) {
    int idx = blockIdx.x * 256 + threadIdx.x;
    if (idx >= 9 * 8 * 8 * 32) return;
    int lane = idx & 31;
    int ni   = (idx >> 5) & 7;
    int k    = (idx >> 8) & 7;
    int t    = idx >> 11;
    int c = 8 * k + (lane & 3);
    int o = 8 * ni + (lane >> 2);
    float b0 = wdef[(o * 64 + c) * 9 + t];
    float b1 = wdef[(o * 64 + c + 4) * 9 + t];
    g_wfrag[idx] = make_float2(__uint_as_float(f2tf32(b0)),
                               __uint_as_float(f2tf32(b1)));
}

// ---------------------------------------------------------------------------
// Kernel 0b: offset-conv B fragments (oc padded 18 -> 24).
// ---------------------------------------------------------------------------
__global__ void wofrag_kernel(const float* __restrict__ woff) {
    int idx = blockIdx.x * 256 + threadIdx.x;
    if (idx >= 72 * 3 * 32) return;
    int lane = idx & 31;
    int rem  = idx >> 5;
    int ni   = rem % 3;
    int ks   = rem / 3;
    int gr = lane >> 2, tc = lane & 3;
    int k0 = 8 * ks + tc;
    int oc = 8 * ni + gr;
    float b0 = (oc < 18) ? woff[oc * 576 + k0]     : 0.0f;
    float b1 = (oc < 18) ? woff[oc * 576 + k0 + 4] : 0.0f;
    g_wofrag[(ks * 3 + ni) * 32 + lane] =
        make_float2(__uint_as_float(f2tf32(b0)), __uint_as_float(f2tf32(b1)));
}

// ---------------------------------------------------------------------------
// Kernel 1: offset conv via tf32 MMA, ROW-PAIR version.
// CTA = 128 threads handles rows (y0, y0+1) x 128 px => M=256.
// smem: 8 channels x 4 input rows (y0-1..y0+2) x 130 cols -> fill/px -33%,
// B-frags amortize over 2x pixels. Warp w: input row = w>>1,
// px base = 64*(w&1), 4 mi-frags (M=64 per warp).
// ---------------------------------------------------------------------------
__global__ void __launch_bounds__(128) offset_mma_kernel(
    const float* __restrict__ xin,
    const float* __restrict__ boff)
{
    __shared__ float sx[32 * XSTR];   // 17408 B

    int tid  = threadIdx.x;
    int lane = tid & 31;
    int warp = tid >> 5;
    int gr   = lane >> 2;
    int tc   = lane & 3;
    int rowsel = warp >> 1;           // 0 -> row y0, 1 -> row y0+1
    int pxb    = 64 * (warp & 1);     // warp's pixel base within 128

    int x0 = blockIdx.x * 128;
    int y0 = blockIdx.y * 2;
    int n  = blockIdx.z;

    float acc[4][3][4];
#pragma unroll
    for (int ni = 0; ni < 3; ni++) {
        int oc = 8 * ni + 2 * tc;
        float blo = (oc < 18)     ? __ldg(&boff[oc])     : 0.0f;
        float bhi = (oc + 1 < 18) ? __ldg(&boff[oc + 1]) : 0.0f;
#pragma unroll
        for (int mi = 0; mi < 4; mi++) {
            acc[mi][ni][0] = blo; acc[mi][ni][1] = bhi;
            acc[mi][ni][2] = blo; acc[mi][ni][3] = bhi;
        }
    }

    const float* xb = xin + (size_t)n * Cc * HW;

    for (int ch = 0; ch < 8; ch++) {
        __syncthreads();
        // fill: 8 channels x 4 rows x 130 cols; r = c*4 + i (shifts, 1 div)
        for (int idx = tid; idx < 4160; idx += 128) {
            int r   = idx / 130;
            int col = idx - 130 * r;
            int c   = r >> 2;
            int i   = r & 3;
            int yy = y0 + i - 1;
            int xx = x0 + col - 1;
            float v = 0.0f;
            if (yy >= 0 && yy < Hh && xx >= 0 && xx < Ww)
                v = xb[(size_t)(ch * 8 + c) * HW + yy * Ww + xx];
            sx[r * XSTR + col] = __uint_as_float(f2tf32(v));
        }
        __syncthreads();

#pragma unroll
        for (int kk = 0; kk < 9; kk++) {
            int kl = 8 * kk + tc;
            int c0 = kl / 9,  t0 = kl - 9 * c0;
            int i0 = t0 / 3,  j0 = t0 - 3 * i0;
            int kl2 = kl + 4;
            int c1 = kl2 / 9, t1 = kl2 - 9 * c1;
            int i1 = t1 / 3,  j1 = t1 - 3 * i1;
            int off0 = ((c0 << 2) + i0 + rowsel) * XSTR + j0 + pxb;
            int off1 = ((c1 << 2) + i1 + rowsel) * XSTR + j1 + pxb;

            const float2* wf = g_wofrag + (size_t)(ch * 9 + kk) * 96;
            float2 bfr[3];
#pragma unroll
            for (int ni = 0; ni < 3; ni++) bfr[ni] = __ldg(&wf[ni * 32 + lane]);

#pragma unroll
            for (int mi = 0; mi < 4; mi++) {
                int m = mi * 16 + gr;
                unsigned a0 = __float_as_uint(sx[off0 + m]);
                unsigned a1 = __float_as_uint(sx[off0 + m + 8]);
                unsigned a2 = __float_as_uint(sx[off1 + m]);
                unsigned a3 = __float_as_uint(sx[off1 + m + 8]);
#pragma unroll
                for (int ni = 0; ni < 3; ni++) {
                    unsigned b0 = __float_as_uint(bfr[ni].x);
                    unsigned b1 = __float_as_uint(bfr[ni].y);
                    asm volatile(
                        "mma.sync.aligned.m16n8k8.row.col.f32.tf32.tf32.f32 "
                        "{%0,%1,%2,%3}, {%4,%5,%6,%7}, {%8,%9}, {%0,%1,%2,%3};"
                        : "+f"(acc[mi][ni][0]), "+f"(acc[mi][ni][1]),
                          "+f"(acc[mi][ni][2]), "+f"(acc[mi][ni][3])
                        : "r"(a0), "r"(a1), "r"(a2), "r"(a3),
                          "r"(b0), "r"(b1));
                }
            }
        }
    }

    // epilogue: warp writes its row (y0+rowsel), pixels [pxb, pxb+64)
    size_t ob = (size_t)n * NOFF * HW + (size_t)(y0 + rowsel) * Ww + x0 + pxb;
#pragma unroll
    for (int ni = 0; ni < 3; ni++) {
        int oc = 8 * ni + 2 * tc;
#pragma unroll
        for (int mi = 0; mi < 4; mi++) {
            int pr = mi * 16 + gr;
            if (oc < 18) {
                g_off[ob + (size_t)oc * HW + pr]     = acc[mi][ni][0];
                g_off[ob + (size_t)oc * HW + pr + 8] = acc[mi][ni][2];
            }
            if (oc + 1 < 18) {
                g_off[ob + (size_t)(oc + 1) * HW + pr]     = acc[mi][ni][1];
                g_off[ob + (size_t)(oc + 1) * HW + pr + 8] = acc[mi][ni][3];
            }
        }
    }
}

// ---------------------------------------------------------------------------
// Kernel 2: deformable conv — Round-9 version verbatim (597 us, verified).
// ---------------------------------------------------------------------------
__global__ void __launch_bounds__(128, 6) deform_mma_kernel(
    const float* __restrict__ xin,
    const float* __restrict__ bdef,
    float* __restrict__ out)
{
    __shared__ __align__(16) float sS[2][64 * SSTR];   // 2 x 17408 B

    int tid  = threadIdx.x;
    int lane = tid & 31;
    int warp = tid >> 5;
    int g    = warp & 1;
    int h    = warp >> 1;
    int gr   = lane >> 2;
    int tc   = lane & 3;

    int x0  = blockIdx.x * 64;
    int y   = blockIdx.y;
    int n   = blockIdx.z;
    int pxl = tid & 63;
    int xg  = x0 + pxl;

    float acc[2][4][4];
#pragma unroll
    for (int ni = 0; ni < 4; ni++) {
        int ni_g = 4 * h + ni;
        float blo = __ldg(&bdef[8 * ni_g + 2 * tc]);
        float bhi = __ldg(&bdef[8 * ni_g + 2 * tc + 1]);
#pragma unroll
        for (int mi = 0; mi < 2; mi++) {
            acc[mi][ni][0] = blo; acc[mi][ni][1] = bhi;
            acc[mi][ni][2] = blo; acc[mi][ni][3] = bhi;
        }
    }

    const float* xb   = xin + (size_t)n * Cc * HW + (size_t)(h * 32) * HW;
    const float* offb = g_off + (size_t)n * NOFF * HW + (size_t)y * Ww + xg;

    float dy = offb[0];
    float dx = offb[(size_t)HW];

    for (int t = 0; t < 9; t++) {
        int i = t / 3, j = t % 3;
        float py  = (float)(y + i - 1) + dy;
        float pxf = (float)(xg + j - 1) + dx;

        if (t < 8) {
            dy = offb[(size_t)(2 * t + 2) * HW];
            dx = offb[(size_t)(2 * t + 3) * HW];
        }

        float fy = floorf(py), fx = floorf(pxf);
        float wy1 = py - fy, wx1 = pxf - fx;
        float wy0 = 1.0f - wy1, wx0 = 1.0f - wx1;
        int iy0 = (int)fy, ix0 = (int)fx;
        int iy1 = iy0 + 1, ix1 = ix0 + 1;

        float gy0 = (iy0 >= 0 && iy0 < Hh) ? wy0 : 0.0f;
        float gy1 = (iy1 >= 0 && iy1 < Hh) ? wy1 : 0.0f;
        float gx0 = (ix0 >= 0 && ix0 < Ww) ? wx0 : 0.0f;
        float gx1 = (ix1 >= 0 && ix1 < Ww) ? wx1 : 0.0f;
        float c00 = gy0 * gx0, c01 = gy0 * gx1;
        float c10 = gy1 * gx0, c11 = gy1 * gx1;

        int yc0 = min(max(iy0, 0), Hh - 1), yc1 = min(max(iy1, 0), Hh - 1);
        int xc0 = min(max(ix0, 0), Ww - 1), xc1 = min(max(ix1, 0), Ww - 1);
        int o00 = yc0 * Ww + xc0, o01 = yc0 * Ww + xc1;
        int o10 = yc1 * Ww + xc0, o11 = yc1 * Ww + xc1;

        float* buf = sS[t & 1];

        {
            float4* srow = (float4*)(buf + pxl * SSTR + 32 * h);
            const float* p = xb;
#pragma unroll
            for (int q = 0; q < 8; q++) {
                float4 v;
                {
                    float a = c00 * p[o00];
                    a = fmaf(c01, p[o01], a);
                    a = fmaf(c10, p[o10], a);
                    a = fmaf(c11, p[o11], a);
                    v.x = __uint_as_float(f2tf32(a));  p += HW;
                }
                {
                    float a = c00 * p[o00];
                    a = fmaf(c01, p[o01], a);
                    a = fmaf(c10, p[o10], a);
                    a = fmaf(c11, p[o11], a);
                    v.y = __uint_as_float(f2tf32(a));  p += HW;
                }
                {
                    float a = c00 * p[o00];
                    a = fmaf(c01, p[o01], a);
                    a = fmaf(c10, p[o10], a);
                    a = fmaf(c11, p[o11], a);
                    v.z = __uint_as_float(f2tf32(a));  p += HW;
                }
                {
                    float a = c00 * p[o00];
                    a = fmaf(c01, p[o01], a);
                    a = fmaf(c10, p[o10], a);
                    a = fmaf(c11, p[o11], a);
                    v.w = __uint_as_float(f2tf32(a));  p += HW;
                }
                srow[q] = v;
            }
        }

        asm volatile("bar.sync %0, %1;" :: "r"(1 + g), "r"(64) : "memory");

        const float2* wf = g_wfrag + (size_t)t * 8 * 8 * 32;
#pragma unroll
        for (int k = 0; k < 8; k++) {
            unsigned a[2][4];
#pragma unroll
            for (int mi = 0; mi < 2; mi++) {
                const float* base = buf + (32 * g + mi * 16 + gr) * SSTR + 8 * k + tc;
                a[mi][0] = __float_as_uint(base[0]);
                a[mi][1] = __float_as_uint(base[8 * SSTR]);
                a[mi][2] = __float_as_uint(base[4]);
                a[mi][3] = __float_as_uint(base[8 * SSTR + 4]);
            }
#pragma unroll
            for (int ni = 0; ni < 4; ni++) {
                int ni_g = 4 * h + ni;
                float2 b = __ldg(&wf[(k * 8 + ni_g) * 32 + lane]);
                unsigned b0 = __float_as_uint(b.x);
                unsigned b1 = __float_as_uint(b.y);
#pragma unroll
                for (int mi = 0; mi < 2; mi++) {
                    asm volatile(
                        "mma.sync.aligned.m16n8k8.row.col.f32.tf32.tf32.f32 "
                        "{%0,%1,%2,%3}, {%4,%5,%6,%7}, {%8,%9}, {%0,%1,%2,%3};"
                        : "+f"(acc[mi][ni][0]), "+f"(acc[mi][ni][1]),
                          "+f"(acc[mi][ni][2]), "+f"(acc[mi][ni][3])
                        : "r"(a[mi][0]), "r"(a[mi][1]), "r"(a[mi][2]), "r"(a[mi][3]),
                          "r"(b0), "r"(b1));
                }
            }
        }
    }

    size_t ob = (size_t)n * CoN * HW + (size_t)y * Ww + x0;
#pragma unroll
    for (int ni = 0; ni < 4; ni++) {
        int o = 8 * (4 * h + ni) + 2 * tc;
#pragma unroll
        for (int mi = 0; mi < 2; mi++) {
            int pr = 32 * g + mi * 16 + gr;
            out[ob + (size_t)o * HW + pr]           = acc[mi][ni][0];
            out[ob + (size_t)(o + 1) * HW + pr]     = acc[mi][ni][1];
            out[ob + (size_t)o * HW + pr + 8]       = acc[mi][ni][2];
            out[ob + (size_t)(o + 1) * HW + pr + 8] = acc[mi][ni][3];
        }
    }
}

// ---------------------------------------------------------------------------
extern "C" void kernel_launch(void* const* d_in, const int* in_sizes, int n_in,
                              void* d_out, int out_size)
{
    const float* x    = (const float*)d_in[0];
    const float* woff = (const float*)d_in[1];
    const float* boff = (const float*)d_in[2];
    const float* wdef = (const float*)d_in[3];
    const float* bdef = (const float*)d_in[4];
    float* out = (float*)d_out;

    wfrag_kernel<<<(9 * 8 * 8 * 32 + 255) / 256, 256>>>(wdef);
    wofrag_kernel<<<(72 * 3 * 32 + 255) / 256, 256>>>(woff);
    offset_mma_kernel<<<dim3(Ww / 128, Hh / 2, Nn), 128>>>(x, boff);
    deform_mma_kernel<<<dim3(Ww / 64, Hh, Nn), 128>>>(x, bdef, out);
}

// round 14
// speedup vs baseline: 1.2135x; 1.0197x over previous
#include <cuda_runtime.h>
#include <cuda_bf16.h>

#define Nn  8
#define Cc  64
#define Hh  128
#define Ww  512
#define CoN 64
#define HW  (Hh * Ww)      // 65536
#define NOFF 18
#define SSTR 68            // deform tile stride: 272B, 16B-aligned, conflict-free
#define XSTR 136           // offset-conv x-tile stride

// Scratch: offsets, channel-quad-packed x, tf32 B-fragment tables.
__device__ float  g_off[(size_t)Nn * NOFF * HW];   // ~36 MB
__device__ float4 g_x4[(size_t)Nn * 16 * HW];      // ~134 MB  [n][c/4][y][x]
__device__ float2 g_wfrag[9 * 8 * 8 * 32];         // deform B frags [t][k][ni][lane]
__device__ float2 g_wofrag[72 * 3 * 32];           // offset B frags

__device__ __forceinline__ unsigned f2tf32(float v) {
    unsigned u;
    asm("cvt.rna.tf32.f32 %0, %1;" : "=r"(u) : "f"(v));
    return u;
}

// ---------------------------------------------------------------------------
// Kernel T: pack x NCHW -> [n][c/4][y][x] float4 (channel-quad interleave).
// Fully coalesced reads (4 strided channel planes) and writes.
// ---------------------------------------------------------------------------
__global__ void __launch_bounds__(256) pack4_kernel(const float* __restrict__ x) {
    int idx = blockIdx.x * 256 + threadIdx.x;   // over Nn*16*HW
    int yx   = idx & (HW - 1);
    int rest = idx >> 16;
    int cq   = rest & 15;
    int n    = rest >> 4;
    const float* src = x + ((size_t)(n * 64 + cq * 4)) * HW + yx;
    g_x4[idx] = make_float4(src[0], src[HW], src[2 * HW], src[3 * HW]);
}

// ---------------------------------------------------------------------------
// Kernel 0a: deform B fragments (m16n8k8 tf32).
// ---------------------------------------------------------------------------
__global__ void wfrag_kernel(const float* __restrict__ wdef) {
    int idx = blockIdx.x * 256 + threadIdx.x;
    if (idx >= 9 * 8 * 8 * 32) return;
    int lane = idx & 31;
    int ni   = (idx >> 5) & 7;
    int k    = (idx >> 8) & 7;
    int t    = idx >> 11;
    int c = 8 * k + (lane & 3);
    int o = 8 * ni + (lane >> 2);
    float b0 = wdef[(o * 64 + c) * 9 + t];
    float b1 = wdef[(o * 64 + c + 4) * 9 + t];
    g_wfrag[idx] = make_float2(__uint_as_float(f2tf32(b0)),
                               __uint_as_float(f2tf32(b1)));
}

// ---------------------------------------------------------------------------
// Kernel 0b: offset-conv B fragments (oc padded 18 -> 24).
// ---------------------------------------------------------------------------
__global__ void wofrag_kernel(const float* __restrict__ woff) {
    int idx = blockIdx.x * 256 + threadIdx.x;
    if (idx >= 72 * 3 * 32) return;
    int lane = idx & 31;
    int rem  = idx >> 5;
    int ni   = rem % 3;
    int ks   = rem / 3;
    int gr = lane >> 2, tc = lane & 3;
    int k0 = 8 * ks + tc;
    int oc = 8 * ni + gr;
    float b0 = (oc < 18) ? woff[oc * 576 + k0]     : 0.0f;
    float b1 = (oc < 18) ? woff[oc * 576 + k0 + 4] : 0.0f;
    g_wofrag[(ks * 3 + ni) * 32 + lane] =
        make_float2(__uint_as_float(f2tf32(b0)), __uint_as_float(f2tf32(b1)));
}

// ---------------------------------------------------------------------------
// Kernel 1: offset conv via tf32 MMA, ROW-PAIR version (Round 13, verbatim).
// ---------------------------------------------------------------------------
__global__ void __launch_bounds__(128) offset_mma_kernel(
    const float* __restrict__ xin,
    const float* __restrict__ boff)
{
    __shared__ float sx[32 * XSTR];   // 17408 B

    int tid  = threadIdx.x;
    int lane = tid & 31;
    int warp = tid >> 5;
    int gr   = lane >> 2;
    int tc   = lane & 3;
    int rowsel = warp >> 1;
    int pxb    = 64 * (warp & 1);

    int x0 = blockIdx.x * 128;
    int y0 = blockIdx.y * 2;
    int n  = blockIdx.z;

    float acc[4][3][4];
#pragma unroll
    for (int ni = 0; ni < 3; ni++) {
        int oc = 8 * ni + 2 * tc;
        float blo = (oc < 18)     ? __ldg(&boff[oc])     : 0.0f;
        float bhi = (oc + 1 < 18) ? __ldg(&boff[oc + 1]) : 0.0f;
#pragma unroll
        for (int mi = 0; mi < 4; mi++) {
            acc[mi][ni][0] = blo; acc[mi][ni][1] = bhi;
            acc[mi][ni][2] = blo; acc[mi][ni][3] = bhi;
        }
    }

    const float* xb = xin + (size_t)n * Cc * HW;

    for (int ch = 0; ch < 8; ch++) {
        __syncthreads();
        for (int idx = tid; idx < 4160; idx += 128) {
            int r   = idx / 130;
            int col = idx - 130 * r;
            int c   = r >> 2;
            int i   = r & 3;
            int yy = y0 + i - 1;
            int xx = x0 + col - 1;
            float v = 0.0f;
            if (yy >= 0 && yy < Hh && xx >= 0 && xx < Ww)
                v = xb[(size_t)(ch * 8 + c) * HW + yy * Ww + xx];
            sx[r * XSTR + col] = __uint_as_float(f2tf32(v));
        }
        __syncthreads();

#pragma unroll
        for (int kk = 0; kk < 9; kk++) {
            int kl = 8 * kk + tc;
            int c0 = kl / 9,  t0 = kl - 9 * c0;
            int i0 = t0 / 3,  j0 = t0 - 3 * i0;
            int kl2 = kl + 4;
            int c1 = kl2 / 9, t1 = kl2 - 9 * c1;
            int i1 = t1 / 3,  j1 = t1 - 3 * i1;
            int off0 = ((c0 << 2) + i0 + rowsel) * XSTR + j0 + pxb;
            int off1 = ((c1 << 2) + i1 + rowsel) * XSTR + j1 + pxb;

            const float2* wf = g_wofrag + (size_t)(ch * 9 + kk) * 96;
            float2 bfr[3];
#pragma unroll
            for (int ni = 0; ni < 3; ni++) bfr[ni] = __ldg(&wf[ni * 32 + lane]);

#pragma unroll
            for (int mi = 0; mi < 4; mi++) {
                int m = mi * 16 + gr;
                unsigned a0 = __float_as_uint(sx[off0 + m]);
                unsigned a1 = __float_as_uint(sx[off0 + m + 8]);
                unsigned a2 = __float_as_uint(sx[off1 + m]);
                unsigned a3 = __float_as_uint(sx[off1 + m + 8]);
#pragma unroll
                for (int ni = 0; ni < 3; ni++) {
                    unsigned b0 = __float_as_uint(bfr[ni].x);
                    unsigned b1 = __float_as_uint(bfr[ni].y);
                    asm volatile(
                        "mma.sync.aligned.m16n8k8.row.col.f32.tf32.tf32.f32 "
                        "{%0,%1,%2,%3}, {%4,%5,%6,%7}, {%8,%9}, {%0,%1,%2,%3};"
                        : "+f"(acc[mi][ni][0]), "+f"(acc[mi][ni][1]),
                          "+f"(acc[mi][ni][2]), "+f"(acc[mi][ni][3])
                        : "r"(a0), "r"(a1), "r"(a2), "r"(a3),
                          "r"(b0), "r"(b1));
                }
            }
        }
    }

    size_t ob = (size_t)n * NOFF * HW + (size_t)(y0 + rowsel) * Ww + x0 + pxb;
#pragma unroll
    for (int ni = 0; ni < 3; ni++) {
        int oc = 8 * ni + 2 * tc;
#pragma unroll
        for (int mi = 0; mi < 4; mi++) {
            int pr = mi * 16 + gr;
            if (oc < 18) {
                g_off[ob + (size_t)oc * HW + pr]     = acc[mi][ni][0];
                g_off[ob + (size_t)oc * HW + pr + 8] = acc[mi][ni][2];
            }
            if (oc + 1 < 18) {
                g_off[ob + (size_t)(oc + 1) * HW + pr]     = acc[mi][ni][1];
                g_off[ob + (size_t)(oc + 1) * HW + pr + 8] = acc[mi][ni][3];
            }
        }
    }
}

// ---------------------------------------------------------------------------
// Kernel 2: deformable conv — Round-9 structure, gather via channel-quad
// LDG.128 from g_x4 (4 channels per load, 16B-aligned, arithmetic identical).
// ---------------------------------------------------------------------------
__global__ void __launch_bounds__(128, 6) deform_mma_kernel(
    const float* __restrict__ bdef,
    float* __restrict__ out)
{
    __shared__ __align__(16) float sS[2][64 * SSTR];   // 2 x 17408 B

    int tid  = threadIdx.x;
    int lane = tid & 31;
    int warp = tid >> 5;
    int g    = warp & 1;
    int h    = warp >> 1;
    int gr   = lane >> 2;
    int tc   = lane & 3;

    int x0  = blockIdx.x * 64;
    int y   = blockIdx.y;
    int n   = blockIdx.z;
    int pxl = tid & 63;
    int xg  = x0 + pxl;

    float acc[2][4][4];
#pragma unroll
    for (int ni = 0; ni < 4; ni++) {
        int ni_g = 4 * h + ni;
        float blo = __ldg(&bdef[8 * ni_g + 2 * tc]);
        float bhi = __ldg(&bdef[8 * ni_g + 2 * tc + 1]);
#pragma unroll
        for (int mi = 0; mi < 2; mi++) {
            acc[mi][ni][0] = blo; acc[mi][ni][1] = bhi;
            acc[mi][ni][2] = blo; acc[mi][ni][3] = bhi;
        }
    }

    const float4* xq  = g_x4 + ((size_t)n * 16 + h * 8) * HW;
    const float* offb = g_off + (size_t)n * NOFF * HW + (size_t)y * Ww + xg;

    float dy = offb[0];
    float dx = offb[(size_t)HW];

    for (int t = 0; t < 9; t++) {
        int i = t / 3, j = t % 3;
        float py  = (float)(y + i - 1) + dy;
        float pxf = (float)(xg + j - 1) + dx;

        if (t < 8) {
            dy = offb[(size_t)(2 * t + 2) * HW];
            dx = offb[(size_t)(2 * t + 3) * HW];
        }

        float fy = floorf(py), fx = floorf(pxf);
        float wy1 = py - fy, wx1 = pxf - fx;
        float wy0 = 1.0f - wy1, wx0 = 1.0f - wx1;
        int iy0 = (int)fy, ix0 = (int)fx;
        int iy1 = iy0 + 1, ix1 = ix0 + 1;

        float gy0 = (iy0 >= 0 && iy0 < Hh) ? wy0 : 0.0f;
        float gy1 = (iy1 >= 0 && iy1 < Hh) ? wy1 : 0.0f;
        float gx0 = (ix0 >= 0 && ix0 < Ww) ? wx0 : 0.0f;
        float gx1 = (ix1 >= 0 && ix1 < Ww) ? wx1 : 0.0f;
        float c00 = gy0 * gx0, c01 = gy0 * gx1;
        float c10 = gy1 * gx0, c11 = gy1 * gx1;

        int yc0 = min(max(iy0, 0), Hh - 1), yc1 = min(max(iy1, 0), Hh - 1);
        int xc0 = min(max(ix0, 0), Ww - 1), xc1 = min(max(ix1, 0), Ww - 1);
        int o00 = yc0 * Ww + xc0, o01 = yc0 * Ww + xc1;
        int o10 = yc1 * Ww + xc0, o11 = yc1 * Ww + xc1;

        float* buf = sS[t & 1];

        {   // gather 8 channel-quads of pixel pxl: 4 x LDG.128 per quad
            float4* srow = (float4*)(buf + pxl * SSTR + 32 * h);
            const float4* p = xq;
#pragma unroll
            for (int q = 0; q < 8; q++) {
                float4 a = p[o00];
                float4 b = p[o01];
                float4 c = p[o10];
                float4 d = p[o11];
                float4 v;
                v.x = fmaf(c11, d.x, fmaf(c10, c.x, fmaf(c01, b.x, c00 * a.x)));
                v.y = fmaf(c11, d.y, fmaf(c10, c.y, fmaf(c01, b.y, c00 * a.y)));
                v.z = fmaf(c11, d.z, fmaf(c10, c.z, fmaf(c01, b.z, c00 * a.z)));
                v.w = fmaf(c11, d.w, fmaf(c10, c.w, fmaf(c01, b.w, c00 * a.w)));
                v.x = __uint_as_float(f2tf32(v.x));
                v.y = __uint_as_float(f2tf32(v.y));
                v.z = __uint_as_float(f2tf32(v.z));
                v.w = __uint_as_float(f2tf32(v.w));
                srow[q] = v;
                p += HW;
            }
        }

        asm volatile("bar.sync %0, %1;" :: "r"(1 + g), "r"(64) : "memory");

        const float2* wf = g_wfrag + (size_t)t * 8 * 8 * 32;
#pragma unroll
        for (int k = 0; k < 8; k++) {
            unsigned a[2][4];
#pragma unroll
            for (int mi = 0; mi < 2; mi++) {
                const float* base = buf + (32 * g + mi * 16 + gr) * SSTR + 8 * k + tc;
                a[mi][0] = __float_as_uint(base[0]);
                a[mi][1] = __float_as_uint(base[8 * SSTR]);
                a[mi][2] = __float_as_uint(base[4]);
                a[mi][3] = __float_as_uint(base[8 * SSTR + 4]);
            }
#pragma unroll
            for (int ni = 0; ni < 4; ni++) {
                int ni_g = 4 * h + ni;
                float2 b = __ldg(&wf[(k * 8 + ni_g) * 32 + lane]);
                unsigned b0 = __float_as_uint(b.x);
                unsigned b1 = __float_as_uint(b.y);
#pragma unroll
                for (int mi = 0; mi < 2; mi++) {
                    asm volatile(
                        "mma.sync.aligned.m16n8k8.row.col.f32.tf32.tf32.f32 "
                        "{%0,%1,%2,%3}, {%4,%5,%6,%7}, {%8,%9}, {%0,%1,%2,%3};"
                        : "+f"(acc[mi][ni][0]), "+f"(acc[mi][ni][1]),
                          "+f"(acc[mi][ni][2]), "+f"(acc[mi][ni][3])
                        : "r"(a[mi][0]), "r"(a[mi][1]), "r"(a[mi][2]), "r"(a[mi][3]),
                          "r"(b0), "r"(b1));
                }
            }
        }
    }

    size_t ob = (size_t)n * CoN * HW + (size_t)y * Ww + x0;
#pragma unroll
    for (int ni = 0; ni < 4; ni++) {
        int o = 8 * (4 * h + ni) + 2 * tc;
#pragma unroll
        for (int mi = 0; mi < 2; mi++) {
            int pr = 32 * g + mi * 16 + gr;
            out[ob + (size_t)o * HW + pr]           = acc[mi][ni][0];
            out[ob + (size_t)(o + 1) * HW + pr]     = acc[mi][ni][1];
            out[ob + (size_t)o * HW + pr + 8]       = acc[mi][ni][2];
            out[ob + (size_t)(o + 1) * HW + pr + 8] = acc[mi][ni][3];
        }
    }
}

// ---------------------------------------------------------------------------
extern "C" void kernel_launch(void* const* d_in, const int* in_sizes, int n_in,
                              void* d_out, int out_size)
{
    const float* x    = (const float*)d_in[0];
    const float* woff = (const float*)d_in[1];
    const float* boff = (const float*)d_in[2];
    const float* wdef = (const float*)d_in[3];
    const float* bdef = (const float*)d_in[4];
    float* out = (float*)d_out;

    wfrag_kernel<<<(9 * 8 * 8 * 32 + 255) / 256, 256>>>(wdef);
    wofrag_kernel<<<(72 * 3 * 32 + 255) / 256, 256>>>(woff);
    pack4_kernel<<<(Nn * 16 * HW) / 256, 256>>>(x);
    offset_mma_kernel<<<dim3(Ww / 128, Hh / 2, Nn), 128>>>(x, boff);
    deform_mma_kernel<<<dim3(Ww / 64, Hh, Nn), 128>>>(bdef, out);
}

// round 15
// speedup vs baseline: 1.3997x; 1.1535x over previous
#include <cuda_runtime.h>
#include <cuda_bf16.h>

#define Nn  8
#define Cc  64
#define Hh  128
#define Ww  512
#define CoN 64
#define HW  (Hh * Ww)      // 65536
#define NOFF 18
#define SSTR 68            // deform tile stride: 272B, 16B-aligned, conflict-free
#define XSTR 136           // offset-conv x-tile stride

// Scratch: offsets, channel-quad-packed x, tf32 B-fragment tables.
__device__ float  g_off[(size_t)Nn * NOFF * HW];   // ~36 MB
__device__ float4 g_x4[(size_t)Nn * 16 * HW];      // ~134 MB  [n][c/4][y][x]
__device__ float2 g_wfrag[9 * 8 * 8 * 32];         // deform B frags [t][k][ni][lane]
__device__ float2 g_wofrag[72 * 3 * 32];           // offset B frags

__device__ __forceinline__ unsigned f2tf32(float v) {
    unsigned u;
    asm("cvt.rna.tf32.f32 %0, %1;" : "=r"(u) : "f"(v));
    return u;
}

// ---------------------------------------------------------------------------
// Kernel T: pack x NCHW -> [n][c/4][y][x] float4 (channel-quad interleave).
// ---------------------------------------------------------------------------
__global__ void __launch_bounds__(256) pack4_kernel(const float* __restrict__ x) {
    int idx = blockIdx.x * 256 + threadIdx.x;   // over Nn*16*HW
    int yx   = idx & (HW - 1);
    int rest = idx >> 16;
    int cq   = rest & 15;
    int n    = rest >> 4;
    const float* src = x + ((size_t)(n * 64 + cq * 4)) * HW + yx;
    g_x4[idx] = make_float4(src[0], src[HW], src[2 * HW], src[3 * HW]);
}

// ---------------------------------------------------------------------------
// Kernel 0a: deform B fragments (m16n8k8 tf32).
// ---------------------------------------------------------------------------
__global__ void wfrag_kernel(const float* __restrict__ wdef) {
    int idx = blockIdx.x * 256 + threadIdx.x;
    if (idx >= 9 * 8 * 8 * 32) return;
    int lane = idx & 31;
    int ni   = (idx >> 5) & 7;
    int k    = (idx >> 8) & 7;
    int t    = idx >> 11;
    int c = 8 * k + (lane & 3);
    int o = 8 * ni + (lane >> 2);
    float b0 = wdef[(o * 64 + c) * 9 + t];
    float b1 = wdef[(o * 64 + c + 4) * 9 + t];
    g_wfrag[idx] = make_float2(__uint_as_float(f2tf32(b0)),
                               __uint_as_float(f2tf32(b1)));
}

// ---------------------------------------------------------------------------
// Kernel 0b: offset-conv B fragments (oc padded 18 -> 24).
// ---------------------------------------------------------------------------
__global__ void wofrag_kernel(const float* __restrict__ woff) {
    int idx = blockIdx.x * 256 + threadIdx.x;
    if (idx >= 72 * 3 * 32) return;
    int lane = idx & 31;
    int rem  = idx >> 5;
    int ni   = rem % 3;
    int ks   = rem / 3;
    int gr = lane >> 2, tc = lane & 3;
    int k0 = 8 * ks + tc;
    int oc = 8 * ni + gr;
    float b0 = (oc < 18) ? woff[oc * 576 + k0]     : 0.0f;
    float b1 = (oc < 18) ? woff[oc * 576 + k0 + 4] : 0.0f;
    g_wofrag[(ks * 3 + ni) * 32 + lane] =
        make_float2(__uint_as_float(f2tf32(b0)), __uint_as_float(f2tf32(b1)));
}

// ---------------------------------------------------------------------------
// Kernel 1: offset conv via tf32 MMA, ROW-PAIR version; smem fill now reads
// channel QUADS from g_x4 (1 LDG.128 = 4 channels) -> 4x fewer fill loads.
// smem image identical to Round 13 (r = c*4 + i), MMA stream unchanged.
// ---------------------------------------------------------------------------
__global__ void __launch_bounds__(128) offset_mma_kernel(
    const float* __restrict__ boff)
{
    __shared__ float sx[32 * XSTR];   // 17408 B

    int tid  = threadIdx.x;
    int lane = tid & 31;
    int warp = tid >> 5;
    int gr   = lane >> 2;
    int tc   = lane & 3;
    int rowsel = warp >> 1;
    int pxb    = 64 * (warp & 1);

    int x0 = blockIdx.x * 128;
    int y0 = blockIdx.y * 2;
    int n  = blockIdx.z;

    float acc[4][3][4];
#pragma unroll
    for (int ni = 0; ni < 3; ni++) {
        int oc = 8 * ni + 2 * tc;
        float blo = (oc < 18)     ? __ldg(&boff[oc])     : 0.0f;
        float bhi = (oc + 1 < 18) ? __ldg(&boff[oc + 1]) : 0.0f;
#pragma unroll
        for (int mi = 0; mi < 4; mi++) {
            acc[mi][ni][0] = blo; acc[mi][ni][1] = bhi;
            acc[mi][ni][2] = blo; acc[mi][ni][3] = bhi;
        }
    }

    const float4* xq = g_x4 + (size_t)n * 16 * HW;

    for (int ch = 0; ch < 8; ch++) {
        __syncthreads();
        // fill: 2 quads x 4 rows x 130 cols = 1040 LDG.128 per chunk.
        // row8 = qi*4 + i; smem rows r = (qi*4+cc)*4 + i (c local = qi*4+cc).
        for (int idx = tid; idx < 1040; idx += 128) {
            int row8 = idx / 130;
            int col  = idx - 130 * row8;
            int qi   = row8 >> 2;
            int i    = row8 & 3;
            int yy = y0 + i - 1;
            int xx = x0 + col - 1;
            float4 v = make_float4(0.f, 0.f, 0.f, 0.f);
            if (yy >= 0 && yy < Hh && xx >= 0 && xx < Ww)
                v = xq[(size_t)(ch * 2 + qi) * HW + yy * Ww + xx];
            int rbase = ((qi << 2) << 2) + i;    // (qi*4+0)*4 + i
            sx[(rbase)      * XSTR + col] = __uint_as_float(f2tf32(v.x));
            sx[(rbase + 4)  * XSTR + col] = __uint_as_float(f2tf32(v.y));
            sx[(rbase + 8)  * XSTR + col] = __uint_as_float(f2tf32(v.z));
            sx[(rbase + 12) * XSTR + col] = __uint_as_float(f2tf32(v.w));
        }
        __syncthreads();

#pragma unroll
        for (int kk = 0; kk < 9; kk++) {
            int kl = 8 * kk + tc;
            int c0 = kl / 9,  t0 = kl - 9 * c0;
            int i0 = t0 / 3,  j0 = t0 - 3 * i0;
            int kl2 = kl + 4;
            int c1 = kl2 / 9, t1 = kl2 - 9 * c1;
            int i1 = t1 / 3,  j1 = t1 - 3 * i1;
            int off0 = ((c0 << 2) + i0 + rowsel) * XSTR + j0 + pxb;
            int off1 = ((c1 << 2) + i1 + rowsel) * XSTR + j1 + pxb;

            const float2* wf = g_wofrag + (size_t)(ch * 9 + kk) * 96;
            float2 bfr[3];
#pragma unroll
            for (int ni = 0; ni < 3; ni++) bfr[ni] = __ldg(&wf[ni * 32 + lane]);

#pragma unroll
            for (int mi = 0; mi < 4; mi++) {
                int m = mi * 16 + gr;
                unsigned a0 = __float_as_uint(sx[off0 + m]);
                unsigned a1 = __float_as_uint(sx[off0 + m + 8]);
                unsigned a2 = __float_as_uint(sx[off1 + m]);
                unsigned a3 = __float_as_uint(sx[off1 + m + 8]);
#pragma unroll
                for (int ni = 0; ni < 3; ni++) {
                    unsigned b0 = __float_as_uint(bfr[ni].x);
                    unsigned b1 = __float_as_uint(bfr[ni].y);
                    asm volatile(
                        "mma.sync.aligned.m16n8k8.row.col.f32.tf32.tf32.f32 "
                        "{%0,%1,%2,%3}, {%4,%5,%6,%7}, {%8,%9}, {%0,%1,%2,%3};"
                        : "+f"(acc[mi][ni][0]), "+f"(acc[mi][ni][1]),
                          "+f"(acc[mi][ni][2]), "+f"(acc[mi][ni][3])
                        : "r"(a0), "r"(a1), "r"(a2), "r"(a3),
                          "r"(b0), "r"(b1));
                }
            }
        }
    }

    size_t ob = (size_t)n * NOFF * HW + (size_t)(y0 + rowsel) * Ww + x0 + pxb;
#pragma unroll
    for (int ni = 0; ni < 3; ni++) {
        int oc = 8 * ni + 2 * tc;
#pragma unroll
        for (int mi = 0; mi < 4; mi++) {
            int pr = mi * 16 + gr;
            if (oc < 18) {
                g_off[ob + (size_t)oc * HW + pr]     = acc[mi][ni][0];
                g_off[ob + (size_t)oc * HW + pr + 8] = acc[mi][ni][2];
            }
            if (oc + 1 < 18) {
                g_off[ob + (size_t)(oc + 1) * HW + pr]     = acc[mi][ni][1];
                g_off[ob + (size_t)(oc + 1) * HW + pr + 8] = acc[mi][ni][3];
            }
        }
    }
}

// ---------------------------------------------------------------------------
// Kernel 2: deformable conv — Round-14 version verbatim (quad-pack gather).
// ---------------------------------------------------------------------------
__global__ void __launch_bounds__(128, 6) deform_mma_kernel(
    const float* __restrict__ bdef,
    float* __restrict__ out)
{
    __shared__ __align__(16) float sS[2][64 * SSTR];   // 2 x 17408 B

    int tid  = threadIdx.x;
    int lane = tid & 31;
    int warp = tid >> 5;
    int g    = warp & 1;
    int h    = warp >> 1;
    int gr   = lane >> 2;
    int tc   = lane & 3;

    int x0  = blockIdx.x * 64;
    int y   = blockIdx.y;
    int n   = blockIdx.z;
    int pxl = tid & 63;
    int xg  = x0 + pxl;

    float acc[2][4][4];
#pragma unroll
    for (int ni = 0; ni < 4; ni++) {
        int ni_g = 4 * h + ni;
        float blo = __ldg(&bdef[8 * ni_g + 2 * tc]);
        float bhi = __ldg(&bdef[8 * ni_g + 2 * tc + 1]);
#pragma unroll
        for (int mi = 0; mi < 2; mi++) {
            acc[mi][ni][0] = blo; acc[mi][ni][1] = bhi;
            acc[mi][ni][2] = blo; acc[mi][ni][3] = bhi;
        }
    }

    const float4* xq  = g_x4 + ((size_t)n * 16 + h * 8) * HW;
    const float* offb = g_off + (size_t)n * NOFF * HW + (size_t)y * Ww + xg;

    float dy = offb[0];
    float dx = offb[(size_t)HW];

    for (int t = 0; t < 9; t++) {
        int i = t / 3, j = t % 3;
        float py  = (float)(y + i - 1) + dy;
        float pxf = (float)(xg + j - 1) + dx;

        if (t < 8) {
            dy = offb[(size_t)(2 * t + 2) * HW];
            dx = offb[(size_t)(2 * t + 3) * HW];
        }

        float fy = floorf(py), fx = floorf(pxf);
        float wy1 = py - fy, wx1 = pxf - fx;
        float wy0 = 1.0f - wy1, wx0 = 1.0f - wx1;
        int iy0 = (int)fy, ix0 = (int)fx;
        int iy1 = iy0 + 1, ix1 = ix0 + 1;

        float gy0 = (iy0 >= 0 && iy0 < Hh) ? wy0 : 0.0f;
        float gy1 = (iy1 >= 0 && iy1 < Hh) ? wy1 : 0.0f;
        float gx0 = (ix0 >= 0 && ix0 < Ww) ? wx0 : 0.0f;
        float gx1 = (ix1 >= 0 && ix1 < Ww) ? wx1 : 0.0f;
        float c00 = gy0 * gx0, c01 = gy0 * gx1;
        float c10 = gy1 * gx0, c11 = gy1 * gx1;

        int yc0 = min(max(iy0, 0), Hh - 1), yc1 = min(max(iy1, 0), Hh - 1);
        int xc0 = min(max(ix0, 0), Ww - 1), xc1 = min(max(ix1, 0), Ww - 1);
        int o00 = yc0 * Ww + xc0, o01 = yc0 * Ww + xc1;
        int o10 = yc1 * Ww + xc0, o11 = yc1 * Ww + xc1;

        float* buf = sS[t & 1];

        {
            float4* srow = (float4*)(buf + pxl * SSTR + 32 * h);
            const float4* p = xq;
#pragma unroll
            for (int q = 0; q < 8; q++) {
                float4 a = p[o00];
                float4 b = p[o01];
                float4 c = p[o10];
                float4 d = p[o11];
                float4 v;
                v.x = fmaf(c11, d.x, fmaf(c10, c.x, fmaf(c01, b.x, c00 * a.x)));
                v.y = fmaf(c11, d.y, fmaf(c10, c.y, fmaf(c01, b.y, c00 * a.y)));
                v.z = fmaf(c11, d.z, fmaf(c10, c.z, fmaf(c01, b.z, c00 * a.z)));
                v.w = fmaf(c11, d.w, fmaf(c10, c.w, fmaf(c01, b.w, c00 * a.w)));
                v.x = __uint_as_float(f2tf32(v.x));
                v.y = __uint_as_float(f2tf32(v.y));
                v.z = __uint_as_float(f2tf32(v.z));
                v.w = __uint_as_float(f2tf32(v.w));
                srow[q] = v;
                p += HW;
            }
        }

        asm volatile("bar.sync %0, %1;" :: "r"(1 + g), "r"(64) : "memory");

        const float2* wf = g_wfrag + (size_t)t * 8 * 8 * 32;
#pragma unroll
        for (int k = 0; k < 8; k++) {
            unsigned a[2][4];
#pragma unroll
            for (int mi = 0; mi < 2; mi++) {
                const float* base = buf + (32 * g + mi * 16 + gr) * SSTR + 8 * k + tc;
                a[mi][0] = __float_as_uint(base[0]);
                a[mi][1] = __float_as_uint(base[8 * SSTR]);
                a[mi][2] = __float_as_uint(base[4]);
                a[mi][3] = __float_as_uint(base[8 * SSTR + 4]);
            }
#pragma unroll
            for (int ni = 0; ni < 4; ni++) {
                int ni_g = 4 * h + ni;
                float2 b = __ldg(&wf[(k * 8 + ni_g) * 32 + lane]);
                unsigned b0 = __float_as_uint(b.x);
                unsigned b1 = __float_as_uint(b.y);
#pragma unroll
                for (int mi = 0; mi < 2; mi++) {
                    asm volatile(
                        "mma.sync.aligned.m16n8k8.row.col.f32.tf32.tf32.f32 "
                        "{%0,%1,%2,%3}, {%4,%5,%6,%7}, {%8,%9}, {%0,%1,%2,%3};"
                        : "+f"(acc[mi][ni][0]), "+f"(acc[mi][ni][1]),
                          "+f"(acc[mi][ni][2]), "+f"(acc[mi][ni][3])
                        : "r"(a[mi][0]), "r"(a[mi][1]), "r"(a[mi][2]), "r"(a[mi][3]),
                          "r"(b0), "r"(b1));
                }
            }
        }
    }

    size_t ob = (size_t)n * CoN * HW + (size_t)y * Ww + x0;
#pragma unroll
    for (int ni = 0; ni < 4; ni++) {
        int o = 8 * (4 * h + ni) + 2 * tc;
#pragma unroll
        for (int mi = 0; mi < 2; mi++) {
            int pr = 32 * g + mi * 16 + gr;
            out[ob + (size_t)o * HW + pr]           = acc[mi][ni][0];
            out[ob + (size_t)(o + 1) * HW + pr]     = acc[mi][ni][1];
            out[ob + (size_t)o * HW + pr + 8]       = acc[mi][ni][2];
            out[ob + (size_t)(o + 1) * HW + pr + 8] = acc[mi][ni][3];
        }
    }
}

// ---------------------------------------------------------------------------
extern "C" void kernel_launch(void* const* d_in, const int* in_sizes, int n_in,
                              void* d_out, int out_size)
{
    const float* x    = (const float*)d_in[0];
    const float* woff = (const float*)d_in[1];
    const float* boff = (const float*)d_in[2];
    const float* wdef = (const float*)d_in[3];
    const float* bdef = (const float*)d_in[4];
    float* out = (float*)d_out;

    wfrag_kernel<<<(9 * 8 * 8 * 32 + 255) / 256, 256>>>(wdef);
    wofrag_kernel<<<(72 * 3 * 32 + 255) / 256, 256>>>(woff);
    pack4_kernel<<<(Nn * 16 * HW) / 256, 256>>>(x);
    offset_mma_kernel<<<dim3(Ww / 128, Hh / 2, Nn), 128>>>(boff);
    deform_mma_kernel<<<dim3(Ww / 64, Hh, Nn), 128>>>(bdef, out);
}